// round 10
// baseline (speedup 1.0000x reference)
#include <cuda_runtime.h>
#include <cuda_bf16.h>
#include <cstdint>

#define BB 64
#define TT 512
#define CC 384
#define HH 64
#define BT (BB*TT)

// Q is pre-scaled by 1/sqrt(64) * log2(e) so attention softmax can use ex2.
#define QSCALE (0.125f * 1.4426950408889634f)

// Scratch for projected Q,K,V (single static device array -- no allocation).
__device__ float g_scratch[3 * BT * HH];
#define g_Q (g_scratch)
#define g_K (g_scratch + BT*HH)
#define g_V (g_scratch + 2*BT*HH)

// ---------------------------------------------------------------------------
// Helpers
// ---------------------------------------------------------------------------
__device__ __forceinline__ float to_tf32(float x) {
    float r;
    asm("cvt.rna.tf32.f32 %0, %1;" : "=f"(r) : "f"(x));
    return r;
}

__device__ __forceinline__ float ex2(float x) {
    float r;
    asm("ex2.approx.f32 %0, %1;" : "=f"(r) : "f"(x));
    return r;
}

__device__ __forceinline__ void mma_tf32(float* c, const uint32_t* a, const uint32_t* b) {
    asm volatile(
        "mma.sync.aligned.m16n8k8.row.col.f32.tf32.tf32.f32 "
        "{%0,%1,%2,%3}, {%4,%5,%6,%7}, {%8,%9}, {%0,%1,%2,%3};"
        : "+f"(c[0]), "+f"(c[1]), "+f"(c[2]), "+f"(c[3])
        : "r"(a[0]), "r"(a[1]), "r"(a[2]), "r"(a[3]),
          "r"(b[0]), "r"(b[1]));
}

// ---------------------------------------------------------------------------
// Fused projection GEMM (TF32 tensor): computes Q,K,V in ONE pass over x.
// grid BT/64 = 512 blocks, 256 threads (8 warps). BM=64, BN=64 (x3 W), BK=32.
// Warp grid: 4 warps on M (wm 0..3 -> 16 rows), 2 on N (wn 0..1 -> 32 cols).
// Per warp per W: 1 m-tile x 4 n-tiles. acc[3][4][4] = 48 regs.
// X tile loaded ONCE and reused for all three weight matrices.
// Wq is pre-scaled by QSCALE (folds softmax scale + log2e into projection).
// ---------------------------------------------------------------------------
__global__ __launch_bounds__(256, 2)
void proj_mma3(const float* __restrict__ x,
               const float* __restrict__ Wq,
               const float* __restrict__ Wk,
               const float* __restrict__ Wv) {
    const int m0 = blockIdx.x * 64;

    __shared__ float Xs[64][36];       // [m][k]
    __shared__ float Ws[3][32][68];    // [w][k][n]

    const int tid  = threadIdx.x;
    const int lane = tid & 31;
    const int warp = tid >> 5;
    const int wm   = warp >> 1;        // 0..3
    const int wn   = warp & 1;         // 0..1
    const int g    = lane >> 2;
    const int t    = lane & 3;

    const uint32_t* Xs32 = (const uint32_t*)&Xs[0][0];

    float acc[3][4][4];
    #pragma unroll
    for (int w = 0; w < 3; w++)
        #pragma unroll
        for (int nt = 0; nt < 4; nt++)
            #pragma unroll
            for (int r = 0; r < 4; r++) acc[w][nt][r] = 0.f;

    for (int k0 = 0; k0 < CC; k0 += 32) {
        // Load X tile 64x32 (512 float4, 2 per thread), cvt to tf32
        #pragma unroll
        for (int i = 0; i < 2; i++) {
            int idx4 = tid + i * 256;          // 0..511
            int m  = idx4 >> 3;
            int c4 = idx4 & 7;
            float4 v = *(const float4*)(x + (size_t)(m0 + m) * CC + k0 + c4 * 4);
            Xs[m][c4 * 4 + 0] = to_tf32(v.x);
            Xs[m][c4 * 4 + 1] = to_tf32(v.y);
            Xs[m][c4 * 4 + 2] = to_tf32(v.z);
            Xs[m][c4 * 4 + 3] = to_tf32(v.w);
        }
        // Load the three W tiles 32x64 each (512 float4 each, 2/thread/W)
        #pragma unroll
        for (int w = 0; w < 3; w++) {
            const float* W = (w == 0) ? Wq : (w == 1 ? Wk : Wv);
            const float sc = (w == 0) ? QSCALE : 1.f;
            #pragma unroll
            for (int i = 0; i < 2; i++) {
                int idx4 = tid + i * 256;
                int k  = idx4 >> 4;
                int n4 = idx4 & 15;
                float4 v = *(const float4*)(W + (size_t)(k0 + k) * HH + n4 * 4);
                Ws[w][k][n4 * 4 + 0] = to_tf32(v.x * sc);
                Ws[w][k][n4 * 4 + 1] = to_tf32(v.y * sc);
                Ws[w][k][n4 * 4 + 2] = to_tf32(v.z * sc);
                Ws[w][k][n4 * 4 + 3] = to_tf32(v.w * sc);
            }
        }
        __syncthreads();

        #pragma unroll
        for (int ks = 0; ks < 4; ks++) {
            const int kk = ks * 8;
            uint32_t a[4];
            {
                int r = wm * 16 + g;
                int c = kk + t;
                a[0] = Xs32[(r)     * 36 + c];
                a[1] = Xs32[(r + 8) * 36 + c];
                a[2] = Xs32[(r)     * 36 + c + 4];
                a[3] = Xs32[(r + 8) * 36 + c + 4];
            }
            #pragma unroll
            for (int w = 0; w < 3; w++) {
                const uint32_t* Wp = (const uint32_t*)&Ws[w][0][0];
                #pragma unroll
                for (int nt = 0; nt < 4; nt++) {
                    int n = wn * 32 + nt * 8 + g;
                    uint32_t bfr[2];
                    bfr[0] = Wp[(kk + t)     * 68 + n];
                    bfr[1] = Wp[(kk + t + 4) * 68 + n];
                    mma_tf32(acc[w][nt], a, bfr);
                }
            }
        }
        __syncthreads();
    }

    // Epilogue: 3 outputs
    #pragma unroll
    for (int w = 0; w < 3; w++) {
        float* Out = g_scratch + (size_t)w * BT * HH;
        int r0 = m0 + wm * 16 + g;
        #pragma unroll
        for (int nt = 0; nt < 4; nt++) {
            int cb = wn * 32 + nt * 8 + 2 * t;
            float2 lo = make_float2(acc[w][nt][0], acc[w][nt][1]);
            float2 hi = make_float2(acc[w][nt][2], acc[w][nt][3]);
            *(float2*)(Out + (size_t)(r0)     * HH + cb) = lo;
            *(float2*)(Out + (size_t)(r0 + 8) * HH + cb) = hi;
        }
    }
}

// ---------------------------------------------------------------------------
// Flash attention on tensor cores (TF32 mma, fp32 accum), base-2 softmax.
// Block: 64 q-rows x one batch, 128 threads (4 warps, 16 q-rows each).
// KV tile = 64. Q A-fragments in registers for the whole kernel.
// launch_bounds(128,4): reg cap 128 -> 4 blocks/SM for latency hiding.
// ---------------------------------------------------------------------------
#define KSTR 72
#define PSTR 76

__global__ __launch_bounds__(128, 4)
void attn3(float* __restrict__ out) {
    const int b    = blockIdx.y;
    const int qb   = blockIdx.x;
    const int q0   = qb * 64;
    const int tid  = threadIdx.x;
    const int lane = tid & 31;
    const int warp = tid >> 5;
    const int g    = lane >> 2;
    const int t    = lane & 3;

    __shared__ __align__(16) float sKP[64 * PSTR];  // Kt (stride 72) / Ps (stride 76)
    __shared__ __align__(16) float sV[64 * KSTR];

    float*    Kt   = sKP;
    float*    Ps   = sKP;
    uint32_t* Kt32 = (uint32_t*)sKP;
    uint32_t* Ps32 = (uint32_t*)sKP;
    uint32_t* Vs32 = (uint32_t*)sV;

    const int r0 = warp * 16 + g;

    // ---- Stage Q (already QSCALE-scaled by proj), extract A-fragments ------
    {
        int q  = tid >> 1;
        int h0 = (tid & 1) * 32;
        const float4* src = (const float4*)(g_Q + (size_t)(b * TT + q0 + q) * HH + h0);
        float* dst = Ps + q * PSTR + h0;
        #pragma unroll
        for (int j = 0; j < 8; j++) {
            float4 v = src[j];
            float4 w;
            w.x = to_tf32(v.x); w.y = to_tf32(v.y);
            w.z = to_tf32(v.z); w.w = to_tf32(v.w);
            *(float4*)(dst + j * 4) = w;
        }
    }
    __syncwarp();

    uint32_t qa[8][4];
    #pragma unroll
    for (int ks = 0; ks < 8; ks++) {
        int c = ks * 8 + t;
        qa[ks][0] = Ps32[(r0)     * PSTR + c];
        qa[ks][1] = Ps32[(r0 + 8) * PSTR + c];
        qa[ks][2] = Ps32[(r0)     * PSTR + c + 4];
        qa[ks][3] = Ps32[(r0 + 8) * PSTR + c + 4];
    }

    float o[8][4];
    #pragma unroll
    for (int nt = 0; nt < 8; nt++)
        #pragma unroll
        for (int r = 0; r < 4; r++) o[nt][r] = 0.f;
    float mr0 = -1e30f, mr1 = -1e30f, l0 = 0.f, l1 = 0.f;

    const int ntiles = qb + 1;
    for (int jt = 0; jt < ntiles; jt++) {
        const int k0 = jt * 64;

        __syncthreads();
        // Load K transposed (tf32): Kt[h][k]
        {
            int k  = tid >> 1;
            int h0 = (tid & 1) * 32;
            const float4* src = (const float4*)(g_K + (size_t)(b * TT + k0 + k) * HH + h0);
            #pragma unroll
            for (int j = 0; j < 8; j++) {
                float4 v = src[j];
                Kt[(h0 + j * 4 + 0) * KSTR + k] = to_tf32(v.x);
                Kt[(h0 + j * 4 + 1) * KSTR + k] = to_tf32(v.y);
                Kt[(h0 + j * 4 + 2) * KSTR + k] = to_tf32(v.z);
                Kt[(h0 + j * 4 + 3) * KSTR + k] = to_tf32(v.w);
            }
        }
        // Load V natural (tf32): Vs[k][h]
        {
            int k  = tid >> 1;
            int h0 = (tid & 1) * 32;
            const float4* src = (const float4*)(g_V + (size_t)(b * TT + k0 + k) * HH + h0);
            float* dst = sV + k * KSTR + h0;
            #pragma unroll
            for (int j = 0; j < 8; j++) {
                float4 v = src[j];
                float4 w;
                w.x = to_tf32(v.x); w.y = to_tf32(v.y);
                w.z = to_tf32(v.z); w.w = to_tf32(v.w);
                *(float4*)(dst + j * 4) = w;
            }
        }
        __syncthreads();

        // ---- GEMM1: S[16x64 per warp] = Qsc @ K^T (logits already x log2e) --
        float s[8][4];
        #pragma unroll
        for (int nt = 0; nt < 8; nt++)
            #pragma unroll
            for (int r = 0; r < 4; r++) s[nt][r] = 0.f;

        #pragma unroll
        for (int ks = 0; ks < 8; ks++) {
            const int kr = ks * 8;
            #pragma unroll
            for (int nt = 0; nt < 8; nt++) {
                uint32_t bf[2];
                bf[0] = Kt32[(kr + t)     * KSTR + nt * 8 + g];
                bf[1] = Kt32[(kr + t + 4) * KSTR + nt * 8 + g];
                mma_tf32(s[nt], qa[ks], bf);
            }
        }

        // ---- Causal mask (diagonal tile only) ------------------------------
        if (jt == qb) {
            #pragma unroll
            for (int nt = 0; nt < 8; nt++) {
                int kc = nt * 8 + 2 * t;
                if (kc     > r0)     s[nt][0] = -1e30f;
                if (kc + 1 > r0)     s[nt][1] = -1e30f;
                if (kc     > r0 + 8) s[nt][2] = -1e30f;
                if (kc + 1 > r0 + 8) s[nt][3] = -1e30f;
            }
        }

        // ---- Online softmax (base-2, registers, quad-shfl reductions) ------
        float mx0 = -1e30f, mx1 = -1e30f;
        #pragma unroll
        for (int nt = 0; nt < 8; nt++) {
            mx0 = fmaxf(mx0, fmaxf(s[nt][0], s[nt][1]));
            mx1 = fmaxf(mx1, fmaxf(s[nt][2], s[nt][3]));
        }
        mx0 = fmaxf(mx0, __shfl_xor_sync(0xffffffffu, mx0, 1));
        mx0 = fmaxf(mx0, __shfl_xor_sync(0xffffffffu, mx0, 2));
        mx1 = fmaxf(mx1, __shfl_xor_sync(0xffffffffu, mx1, 1));
        mx1 = fmaxf(mx1, __shfl_xor_sync(0xffffffffu, mx1, 2));

        float nm0 = fmaxf(mr0, mx0), nm1 = fmaxf(mr1, mx1);
        float a0 = ex2(mr0 - nm0), a1 = ex2(mr1 - nm1);
        mr0 = nm0; mr1 = nm1;

        float ls0 = 0.f, ls1 = 0.f;
        #pragma unroll
        for (int nt = 0; nt < 8; nt++) {
            s[nt][0] = ex2(s[nt][0] - nm0);
            s[nt][1] = ex2(s[nt][1] - nm0);
            s[nt][2] = ex2(s[nt][2] - nm1);
            s[nt][3] = ex2(s[nt][3] - nm1);
            ls0 += s[nt][0] + s[nt][1];
            ls1 += s[nt][2] + s[nt][3];
        }
        ls0 += __shfl_xor_sync(0xffffffffu, ls0, 1);
        ls0 += __shfl_xor_sync(0xffffffffu, ls0, 2);
        ls1 += __shfl_xor_sync(0xffffffffu, ls1, 1);
        ls1 += __shfl_xor_sync(0xffffffffu, ls1, 2);
        l0 = l0 * a0 + ls0;
        l1 = l1 * a1 + ls1;
        #pragma unroll
        for (int nt = 0; nt < 8; nt++) {
            o[nt][0] *= a0; o[nt][1] *= a0;
            o[nt][2] *= a1; o[nt][3] *= a1;
        }

        __syncthreads();   // all warps done reading Kt before P overlays it

        // ---- Store P (tf32) into Ps[q][k] ---------------------------------
        #pragma unroll
        for (int nt = 0; nt < 8; nt++) {
            int kc = nt * 8 + 2 * t;
            float2 p0 = make_float2(to_tf32(s[nt][0]), to_tf32(s[nt][1]));
            float2 p1 = make_float2(to_tf32(s[nt][2]), to_tf32(s[nt][3]));
            *(float2*)(Ps + (r0)     * PSTR + kc) = p0;
            *(float2*)(Ps + (r0 + 8) * PSTR + kc) = p1;
        }
        __syncwarp();

        // ---- GEMM2: O[16x64 per warp] += P @ V -----------------------------
        #pragma unroll
        for (int ks = 0; ks < 8; ks++) {
            const int kr = ks * 8;
            uint32_t pa[4];
            pa[0] = Ps32[(r0)     * PSTR + kr + t];
            pa[1] = Ps32[(r0 + 8) * PSTR + kr + t];
            pa[2] = Ps32[(r0)     * PSTR + kr + t + 4];
            pa[3] = Ps32[(r0 + 8) * PSTR + kr + t + 4];
            #pragma unroll
            for (int nt = 0; nt < 8; nt++) {
                uint32_t bf[2];
                bf[0] = Vs32[(kr + t)     * KSTR + nt * 8 + g];
                bf[1] = Vs32[(kr + t + 4) * KSTR + nt * 8 + g];
                mma_tf32(o[nt], pa, bf);
            }
        }
    }

    // ---- Normalize + store --------------------------------------------------
    const float inv0 = 1.f / l0;
    const float inv1 = 1.f / l1;
    #pragma unroll
    for (int nt = 0; nt < 8; nt++) {
        int cb = nt * 8 + 2 * t;
        float2 lo = make_float2(o[nt][0] * inv0, o[nt][1] * inv0);
        float2 hi = make_float2(o[nt][2] * inv1, o[nt][3] * inv1);
        *(float2*)(out + (size_t)(b * TT + q0 + r0)     * HH + cb) = lo;
        *(float2*)(out + (size_t)(b * TT + q0 + r0 + 8) * HH + cb) = hi;
    }
}

// ---------------------------------------------------------------------------
extern "C" void kernel_launch(void* const* d_in, const int* in_sizes, int n_in,
                              void* d_out, int out_size) {
    const float* x  = (const float*)d_in[0];
    const float* Wq = (const float*)d_in[1];
    const float* Wk = (const float*)d_in[2];
    const float* Wv = (const float*)d_in[3];
    float* out = (float*)d_out;

    proj_mma3<<<BT / 64, 256>>>(x, Wq, Wk, Wv);
    attn3<<<dim3(TT / 64, BB), 128>>>(out);
}

// round 12
// speedup vs baseline: 1.2166x; 1.2166x over previous
#include <cuda_runtime.h>
#include <cuda_bf16.h>
#include <cstdint>

#define BB 64
#define TT 512
#define CC 384
#define HH 64
#define BT (BB*TT)

// Q is pre-scaled by 1/sqrt(64) * log2(e) so attention softmax can use ex2.
#define QSCALE (0.125f * 1.4426950408889634f)

// Scratch for projected Q,K,V (single static device array -- no allocation).
__device__ float g_scratch[3 * BT * HH];
#define g_Q (g_scratch)
#define g_K (g_scratch + BT*HH)
#define g_V (g_scratch + 2*BT*HH)

// ---------------------------------------------------------------------------
// Helpers
// ---------------------------------------------------------------------------
__device__ __forceinline__ float to_tf32(float x) {
    float r;
    asm("cvt.rna.tf32.f32 %0, %1;" : "=f"(r) : "f"(x));
    return r;
}

__device__ __forceinline__ float ex2(float x) {
    float r;
    asm("ex2.approx.f32 %0, %1;" : "=f"(r) : "f"(x));
    return r;
}

__device__ __forceinline__ void mma_tf32(float* c, const uint32_t* a, const uint32_t* b) {
    asm volatile(
        "mma.sync.aligned.m16n8k8.row.col.f32.tf32.tf32.f32 "
        "{%0,%1,%2,%3}, {%4,%5,%6,%7}, {%8,%9}, {%0,%1,%2,%3};"
        : "+f"(c[0]), "+f"(c[1]), "+f"(c[2]), "+f"(c[3])
        : "r"(a[0]), "r"(a[1]), "r"(a[2]), "r"(a[3]),
          "r"(b[0]), "r"(b[1]));
}

// ---------------------------------------------------------------------------
// Projection GEMM (TF32 tensor): Out[BT x 64] = x[BT x 384] @ W[384 x 64].
// R7/R8 configuration (measured ~64us). grid (BT/128, 3), block 256.
// BM=128, BN=64, BK=32. Wq pre-scaled by QSCALE.
// ---------------------------------------------------------------------------
__global__ __launch_bounds__(256, 2)
void proj_mma(const float* __restrict__ x,
              const float* __restrict__ Wq,
              const float* __restrict__ Wk,
              const float* __restrict__ Wv) {
    const int m0 = blockIdx.x * 128;
    const float* W = (blockIdx.y == 0) ? Wq : (blockIdx.y == 1 ? Wk : Wv);
    const float sc = (blockIdx.y == 0) ? QSCALE : 1.f;
    float* Out = g_scratch + (size_t)blockIdx.y * BT * HH;

    __shared__ float Xs[128][36];
    __shared__ float Ws[32][68];

    const int tid  = threadIdx.x;
    const int lane = tid & 31;
    const int warp = tid >> 5;
    const int wm   = warp >> 1;
    const int wn   = warp & 1;
    const int g    = lane >> 2;
    const int t    = lane & 3;

    const uint32_t* Xs32 = (const uint32_t*)&Xs[0][0];
    const uint32_t* Ws32 = (const uint32_t*)&Ws[0][0];

    float acc[2][4][4];
    #pragma unroll
    for (int mt = 0; mt < 2; mt++)
        #pragma unroll
        for (int nt = 0; nt < 4; nt++)
            #pragma unroll
            for (int r = 0; r < 4; r++) acc[mt][nt][r] = 0.f;

    for (int k0 = 0; k0 < CC; k0 += 32) {
        #pragma unroll
        for (int i = 0; i < 4; i++) {
            int idx4 = tid + i * 256;
            int m  = idx4 >> 3;
            int c4 = idx4 & 7;
            float4 v = *(const float4*)(x + (size_t)(m0 + m) * CC + k0 + c4 * 4);
            Xs[m][c4 * 4 + 0] = to_tf32(v.x);
            Xs[m][c4 * 4 + 1] = to_tf32(v.y);
            Xs[m][c4 * 4 + 2] = to_tf32(v.z);
            Xs[m][c4 * 4 + 3] = to_tf32(v.w);
        }
        #pragma unroll
        for (int i = 0; i < 2; i++) {
            int idx4 = tid + i * 256;
            int k  = idx4 >> 4;
            int n4 = idx4 & 15;
            float4 v = *(const float4*)(W + (size_t)(k0 + k) * HH + n4 * 4);
            Ws[k][n4 * 4 + 0] = to_tf32(v.x * sc);
            Ws[k][n4 * 4 + 1] = to_tf32(v.y * sc);
            Ws[k][n4 * 4 + 2] = to_tf32(v.z * sc);
            Ws[k][n4 * 4 + 3] = to_tf32(v.w * sc);
        }
        __syncthreads();

        #pragma unroll
        for (int ks = 0; ks < 4; ks++) {
            const int kk = ks * 8;
            uint32_t a[2][4], bfr[4][2];
            #pragma unroll
            for (int mt = 0; mt < 2; mt++) {
                int r = wm * 32 + mt * 16 + g;
                int c = kk + t;
                a[mt][0] = Xs32[(r)     * 36 + c];
                a[mt][1] = Xs32[(r + 8) * 36 + c];
                a[mt][2] = Xs32[(r)     * 36 + c + 4];
                a[mt][3] = Xs32[(r + 8) * 36 + c + 4];
            }
            #pragma unroll
            for (int nt = 0; nt < 4; nt++) {
                int n = wn * 32 + nt * 8 + g;
                bfr[nt][0] = Ws32[(kk + t)     * 68 + n];
                bfr[nt][1] = Ws32[(kk + t + 4) * 68 + n];
            }
            #pragma unroll
            for (int mt = 0; mt < 2; mt++)
                #pragma unroll
                for (int nt = 0; nt < 4; nt++)
                    mma_tf32(acc[mt][nt], a[mt], bfr[nt]);
        }
        __syncthreads();
    }

    #pragma unroll
    for (int mt = 0; mt < 2; mt++) {
        int r0 = m0 + wm * 32 + mt * 16 + g;
        #pragma unroll
        for (int nt = 0; nt < 4; nt++) {
            int cb = wn * 32 + nt * 8 + 2 * t;
            float2 lo = make_float2(acc[mt][nt][0], acc[mt][nt][1]);
            float2 hi = make_float2(acc[mt][nt][2], acc[mt][nt][3]);
            *(float2*)(Out + (size_t)(r0)     * HH + cb) = lo;
            *(float2*)(Out + (size_t)(r0 + 8) * HH + cb) = hi;
        }
    }
}

// ---------------------------------------------------------------------------
// Flash attention on tensor cores (TF32 mma, fp32 accum), base-2 softmax.
// Block: 64 q-rows x one batch, 128 threads (4 warps). KV tile = 64.
// K kept in NATURAL [key][h] layout (mma.row.col's B operand IS K-natural) --
// no transpose, vectorized float4 stores.
// smem: sKP = union{ Ks[64][76] (GEMM1 B) / Ps[64][76] (GEMM2 A) },
//       sV[64][72] (GEMM2 B). Stride 76 (12 mod 32): B-frag reads
//       (g*12+t distinct) AND A-frag reads conflict-free. Stride 72 (8 mod
//       32): V B-frag reads (t*8+g) conflict-free.
// ---------------------------------------------------------------------------
#define VSTR 72
#define PSTR 76

__global__ __launch_bounds__(128)
void attn4(float* __restrict__ out) {
    const int b    = blockIdx.y;
    const int qb   = blockIdx.x;
    const int q0   = qb * 64;
    const int tid  = threadIdx.x;
    const int lane = tid & 31;
    const int warp = tid >> 5;
    const int g    = lane >> 2;
    const int t    = lane & 3;

    __shared__ __align__(16) float sKP[64 * PSTR];  // Ks / Ps overlay
    __shared__ __align__(16) float sV[64 * VSTR];

    float*    Ks   = sKP;
    float*    Ps   = sKP;
    uint32_t* Ks32 = (uint32_t*)sKP;
    uint32_t* Ps32 = (uint32_t*)sKP;
    uint32_t* Vs32 = (uint32_t*)sV;

    const int r0 = warp * 16 + g;

    // ---- Stage Q (already QSCALE*log2e-scaled by proj), extract A-frags ----
    {
        int q  = tid >> 1;
        int h0 = (tid & 1) * 32;
        const float4* src = (const float4*)(g_Q + (size_t)(b * TT + q0 + q) * HH + h0);
        float* dst = Ps + q * PSTR + h0;
        #pragma unroll
        for (int j = 0; j < 8; j++) {
            float4 v = src[j];
            float4 w;
            w.x = to_tf32(v.x); w.y = to_tf32(v.y);
            w.z = to_tf32(v.z); w.w = to_tf32(v.w);
            *(float4*)(dst + j * 4) = w;
        }
    }
    __syncwarp();   // staging rows are warp-local

    uint32_t qa[8][4];
    #pragma unroll
    for (int ks = 0; ks < 8; ks++) {
        int c = ks * 8 + t;
        qa[ks][0] = Ps32[(r0)     * PSTR + c];
        qa[ks][1] = Ps32[(r0 + 8) * PSTR + c];
        qa[ks][2] = Ps32[(r0)     * PSTR + c + 4];
        qa[ks][3] = Ps32[(r0 + 8) * PSTR + c + 4];
    }

    float o[8][4];
    #pragma unroll
    for (int nt = 0; nt < 8; nt++)
        #pragma unroll
        for (int r = 0; r < 4; r++) o[nt][r] = 0.f;
    float mr0 = -1e30f, mr1 = -1e30f, l0 = 0.f, l1 = 0.f;

    const int ntiles = qb + 1;
    for (int jt = 0; jt < ntiles; jt++) {
        const int k0 = jt * 64;

        __syncthreads();   // prev tile's GEMM2 done with Vs/Ps
        // Load K NATURAL (tf32): Ks[key][h] -- vectorized, no transpose
        {
            int k  = tid >> 1;
            int h0 = (tid & 1) * 32;
            const float4* src = (const float4*)(g_K + (size_t)(b * TT + k0 + k) * HH + h0);
            float* dst = Ks + k * PSTR + h0;
            #pragma unroll
            for (int j = 0; j < 8; j++) {
                float4 v = src[j];
                float4 w;
                w.x = to_tf32(v.x); w.y = to_tf32(v.y);
                w.z = to_tf32(v.z); w.w = to_tf32(v.w);
                *(float4*)(dst + j * 4) = w;
            }
        }
        // Load V natural (tf32): Vs[key][h]
        {
            int k  = tid >> 1;
            int h0 = (tid & 1) * 32;
            const float4* src = (const float4*)(g_V + (size_t)(b * TT + k0 + k) * HH + h0);
            float* dst = sV + k * VSTR + h0;
            #pragma unroll
            for (int j = 0; j < 8; j++) {
                float4 v = src[j];
                float4 w;
                w.x = to_tf32(v.x); w.y = to_tf32(v.y);
                w.z = to_tf32(v.z); w.w = to_tf32(v.w);
                *(float4*)(dst + j * 4) = w;
            }
        }
        __syncthreads();

        // ---- GEMM1: S[16x64 per warp] = Qsc @ K^T --------------------------
        // B-frag from natural K: B[k_mma=h][n=key] = Ks[key][h]
        float s[8][4];
        #pragma unroll
        for (int nt = 0; nt < 8; nt++)
            #pragma unroll
            for (int r = 0; r < 4; r++) s[nt][r] = 0.f;

        #pragma unroll
        for (int ks = 0; ks < 8; ks++) {
            const int kr = ks * 8;
            #pragma unroll
            for (int nt = 0; nt < 8; nt++) {
                uint32_t bf[2];
                bf[0] = Ks32[(nt * 8 + g) * PSTR + kr + t];
                bf[1] = Ks32[(nt * 8 + g) * PSTR + kr + t + 4];
                mma_tf32(s[nt], qa[ks], bf);
            }
        }

        // ---- Causal mask (diagonal tile only) ------------------------------
        if (jt == qb) {
            #pragma unroll
            for (int nt = 0; nt < 8; nt++) {
                int kc = nt * 8 + 2 * t;
                if (kc     > r0)     s[nt][0] = -1e30f;
                if (kc + 1 > r0)     s[nt][1] = -1e30f;
                if (kc     > r0 + 8) s[nt][2] = -1e30f;
                if (kc + 1 > r0 + 8) s[nt][3] = -1e30f;
            }
        }

        // ---- Online softmax (base-2, registers, quad-shfl reductions) ------
        float mx0 = -1e30f, mx1 = -1e30f;
        #pragma unroll
        for (int nt = 0; nt < 8; nt++) {
            mx0 = fmaxf(mx0, fmaxf(s[nt][0], s[nt][1]));
            mx1 = fmaxf(mx1, fmaxf(s[nt][2], s[nt][3]));
        }
        mx0 = fmaxf(mx0, __shfl_xor_sync(0xffffffffu, mx0, 1));
        mx0 = fmaxf(mx0, __shfl_xor_sync(0xffffffffu, mx0, 2));
        mx1 = fmaxf(mx1, __shfl_xor_sync(0xffffffffu, mx1, 1));
        mx1 = fmaxf(mx1, __shfl_xor_sync(0xffffffffu, mx1, 2));

        float nm0 = fmaxf(mr0, mx0), nm1 = fmaxf(mr1, mx1);
        float a0 = ex2(mr0 - nm0), a1 = ex2(mr1 - nm1);
        mr0 = nm0; mr1 = nm1;

        float ls0 = 0.f, ls1 = 0.f;
        #pragma unroll
        for (int nt = 0; nt < 8; nt++) {
            s[nt][0] = ex2(s[nt][0] - nm0);
            s[nt][1] = ex2(s[nt][1] - nm0);
            s[nt][2] = ex2(s[nt][2] - nm1);
            s[nt][3] = ex2(s[nt][3] - nm1);
            ls0 += s[nt][0] + s[nt][1];
            ls1 += s[nt][2] + s[nt][3];
        }
        ls0 += __shfl_xor_sync(0xffffffffu, ls0, 1);
        ls0 += __shfl_xor_sync(0xffffffffu, ls0, 2);
        ls1 += __shfl_xor_sync(0xffffffffu, ls1, 1);
        ls1 += __shfl_xor_sync(0xffffffffu, ls1, 2);
        l0 = l0 * a0 + ls0;
        l1 = l1 * a1 + ls1;
        #pragma unroll
        for (int nt = 0; nt < 8; nt++) {
            o[nt][0] *= a0; o[nt][1] *= a0;
            o[nt][2] *= a1; o[nt][3] *= a1;
        }

        __syncthreads();   // all warps done reading Ks before P overlays it

        // ---- Store P (tf32) into Ps[q][k] ---------------------------------
        #pragma unroll
        for (int nt = 0; nt < 8; nt++) {
            int kc = nt * 8 + 2 * t;
            float2 p0 = make_float2(to_tf32(s[nt][0]), to_tf32(s[nt][1]));
            float2 p1 = make_float2(to_tf32(s[nt][2]), to_tf32(s[nt][3]));
            *(float2*)(Ps + (r0)     * PSTR + kc) = p0;
            *(float2*)(Ps + (r0 + 8) * PSTR + kc) = p1;
        }
        __syncwarp();      // P rows are warp-local

        // ---- GEMM2: O[16x64 per warp] += P @ V -----------------------------
        #pragma unroll
        for (int ks = 0; ks < 8; ks++) {
            const int kr = ks * 8;
            uint32_t pa[4];
            pa[0] = Ps32[(r0)     * PSTR + kr + t];
            pa[1] = Ps32[(r0 + 8) * PSTR + kr + t];
            pa[2] = Ps32[(r0)     * PSTR + kr + t + 4];
            pa[3] = Ps32[(r0 + 8) * PSTR + kr + t + 4];
            #pragma unroll
            for (int nt = 0; nt < 8; nt++) {
                uint32_t bf[2];
                bf[0] = Vs32[(kr + t)     * VSTR + nt * 8 + g];
                bf[1] = Vs32[(kr + t + 4) * VSTR + nt * 8 + g];
                mma_tf32(o[nt], pa, bf);
            }
        }
    }

    // ---- Normalize + store --------------------------------------------------
    const float inv0 = 1.f / l0;
    const float inv1 = 1.f / l1;
    #pragma unroll
    for (int nt = 0; nt < 8; nt++) {
        int cb = nt * 8 + 2 * t;
        float2 lo = make_float2(o[nt][0] * inv0, o[nt][1] * inv0);
        float2 hi = make_float2(o[nt][2] * inv1, o[nt][3] * inv1);
        *(float2*)(out + (size_t)(b * TT + q0 + r0)     * HH + cb) = lo;
        *(float2*)(out + (size_t)(b * TT + q0 + r0 + 8) * HH + cb) = hi;
    }
}

// ---------------------------------------------------------------------------
extern "C" void kernel_launch(void* const* d_in, const int* in_sizes, int n_in,
                              void* d_out, int out_size) {
    const float* x  = (const float*)d_in[0];
    const float* Wq = (const float*)d_in[1];
    const float* Wk = (const float*)d_in[2];
    const float* Wv = (const float*)d_in[3];
    float* out = (float*)d_out;

    proj_mma<<<dim3(BT / 128, 3), 256>>>(x, Wq, Wk, Wv);
    attn4<<<dim3(TT / 64, BB), 128>>>(out);
}

// round 15
// speedup vs baseline: 1.2969x; 1.0660x over previous
#include <cuda_runtime.h>
#include <cuda_bf16.h>
#include <cstdint>

#define BB 64
#define TT 512
#define CC 384
#define HH 64
#define BT (BB*TT)

// Q is pre-scaled by 1/sqrt(64) * log2(e) so attention softmax can use ex2.
#define QSCALE (0.125f * 1.4426950408889634f)

// Scratch for projected Q,K,V (single static device array -- no allocation).
__device__ float g_scratch[3 * BT * HH];
#define g_Q (g_scratch)
#define g_K (g_scratch + BT*HH)
#define g_V (g_scratch + 2*BT*HH)

// ---------------------------------------------------------------------------
// Helpers
// ---------------------------------------------------------------------------
__device__ __forceinline__ float to_tf32(float x) {
    float r;
    asm("cvt.rna.tf32.f32 %0, %1;" : "=f"(r) : "f"(x));
    return r;
}

__device__ __forceinline__ float ex2(float x) {
    float r;
    asm("ex2.approx.f32 %0, %1;" : "=f"(r) : "f"(x));
    return r;
}

__device__ __forceinline__ void mma_tf32(float* c, const uint32_t* a, const uint32_t* b) {
    asm volatile(
        "mma.sync.aligned.m16n8k8.row.col.f32.tf32.tf32.f32 "
        "{%0,%1,%2,%3}, {%4,%5,%6,%7}, {%8,%9}, {%0,%1,%2,%3};"
        : "+f"(c[0]), "+f"(c[1]), "+f"(c[2]), "+f"(c[3])
        : "r"(a[0]), "r"(a[1]), "r"(a[2]), "r"(a[3]),
          "r"(b[0]), "r"(b[1]));
}

// ---------------------------------------------------------------------------
// Projection GEMM (TF32 tensor): Out[BT x 64] = x[BT x 384] @ W[384 x 64].
// grid (BT/128, 3), block 256. BM=128, BN=64, BK=32. Wq pre-scaled.
// Register-prefetch pipeline: LDG for k-step k0+32 issued right after the
// post-STS barrier, hidden behind the mma section.
// ---------------------------------------------------------------------------
__global__ __launch_bounds__(256, 2)
void proj_mma(const float* __restrict__ x,
              const float* __restrict__ Wq,
              const float* __restrict__ Wk,
              const float* __restrict__ Wv) {
    const int m0 = blockIdx.x * 128;
    const float* W = (blockIdx.y == 0) ? Wq : (blockIdx.y == 1 ? Wk : Wv);
    const float sc = (blockIdx.y == 0) ? QSCALE : 1.f;
    float* Out = g_scratch + (size_t)blockIdx.y * BT * HH;

    __shared__ float Xs[128][36];
    __shared__ float Ws[32][68];

    const int tid  = threadIdx.x;
    const int lane = tid & 31;
    const int warp = tid >> 5;
    const int wm   = warp >> 1;
    const int wn   = warp & 1;
    const int g    = lane >> 2;
    const int t    = lane & 3;

    const uint32_t* Xs32 = (const uint32_t*)&Xs[0][0];
    const uint32_t* Ws32 = (const uint32_t*)&Ws[0][0];

    float acc[2][4][4];
    #pragma unroll
    for (int mt = 0; mt < 2; mt++)
        #pragma unroll
        for (int nt = 0; nt < 4; nt++)
            #pragma unroll
            for (int r = 0; r < 4; r++) acc[mt][nt][r] = 0.f;

    // Per-thread load coordinates
    const int xm[4] = { (tid + 0)   >> 3, (tid + 256) >> 3,
                        (tid + 512) >> 3, (tid + 768) >> 3 };
    const int xc = (tid & 7) * 4;
    const int wk[2] = { tid >> 4, (tid + 256) >> 4 };
    const int wn4 = (tid & 15) * 4;

    float4 xr[4], wr[2];
    // Preamble: load k0 = 0
    #pragma unroll
    for (int i = 0; i < 4; i++)
        xr[i] = *(const float4*)(x + (size_t)(m0 + xm[i]) * CC + xc);
    #pragma unroll
    for (int i = 0; i < 2; i++)
        wr[i] = *(const float4*)(W + (size_t)wk[i] * HH + wn4);

    for (int k0 = 0; k0 < CC; k0 += 32) {
        // STS current tiles (cvt to tf32)
        #pragma unroll
        for (int i = 0; i < 4; i++) {
            Xs[xm[i]][xc + 0] = to_tf32(xr[i].x);
            Xs[xm[i]][xc + 1] = to_tf32(xr[i].y);
            Xs[xm[i]][xc + 2] = to_tf32(xr[i].z);
            Xs[xm[i]][xc + 3] = to_tf32(xr[i].w);
        }
        #pragma unroll
        for (int i = 0; i < 2; i++) {
            Ws[wk[i]][wn4 + 0] = to_tf32(wr[i].x * sc);
            Ws[wk[i]][wn4 + 1] = to_tf32(wr[i].y * sc);
            Ws[wk[i]][wn4 + 2] = to_tf32(wr[i].z * sc);
            Ws[wk[i]][wn4 + 3] = to_tf32(wr[i].w * sc);
        }
        __syncthreads();

        // Prefetch next k-step (hidden behind mma section)
        if (k0 + 32 < CC) {
            #pragma unroll
            for (int i = 0; i < 4; i++)
                xr[i] = *(const float4*)(x + (size_t)(m0 + xm[i]) * CC + k0 + 32 + xc);
            #pragma unroll
            for (int i = 0; i < 2; i++)
                wr[i] = *(const float4*)(W + (size_t)(k0 + 32 + wk[i]) * HH + wn4);
        }

        #pragma unroll
        for (int ks = 0; ks < 4; ks++) {
            const int kk = ks * 8;
            uint32_t a[2][4], bfr[4][2];
            #pragma unroll
            for (int mt = 0; mt < 2; mt++) {
                int r = wm * 32 + mt * 16 + g;
                int c = kk + t;
                a[mt][0] = Xs32[(r)     * 36 + c];
                a[mt][1] = Xs32[(r + 8) * 36 + c];
                a[mt][2] = Xs32[(r)     * 36 + c + 4];
                a[mt][3] = Xs32[(r + 8) * 36 + c + 4];
            }
            #pragma unroll
            for (int nt = 0; nt < 4; nt++) {
                int n = wn * 32 + nt * 8 + g;
                bfr[nt][0] = Ws32[(kk + t)     * 68 + n];
                bfr[nt][1] = Ws32[(kk + t + 4) * 68 + n];
            }
            #pragma unroll
            for (int mt = 0; mt < 2; mt++)
                #pragma unroll
                for (int nt = 0; nt < 4; nt++)
                    mma_tf32(acc[mt][nt], a[mt], bfr[nt]);
        }
        __syncthreads();
    }

    #pragma unroll
    for (int mt = 0; mt < 2; mt++) {
        int r0 = m0 + wm * 32 + mt * 16 + g;
        #pragma unroll
        for (int nt = 0; nt < 4; nt++) {
            int cb = wn * 32 + nt * 8 + 2 * t;
            float2 lo = make_float2(acc[mt][nt][0], acc[mt][nt][1]);
            float2 hi = make_float2(acc[mt][nt][2], acc[mt][nt][3]);
            *(float2*)(Out + (size_t)(r0)     * HH + cb) = lo;
            *(float2*)(Out + (size_t)(r0 + 8) * HH + cb) = hi;
        }
    }
}

// ---------------------------------------------------------------------------
// Flash attention on tensor cores (TF32 mma, fp32 accum), base-2 softmax.
// Block: 64 q-rows x one batch, 128 threads (4 warps). KV tile = 64.
// Single-buffer register prefetch pipeline (pf[8]): every K/V LDG is issued
// at least one compute phase before its consumption -> no exposed LDG.
// Reversed qb order: longest (most-tiles) blocks dispatched first.
// smem: sKP = union{ Ks[64][76] / Ps[64][76] }, sV[64][72].
// ---------------------------------------------------------------------------
#define VSTR 72
#define PSTR 76

__global__ __launch_bounds__(128)
void attn5(float* __restrict__ out) {
    const int b    = blockIdx.y;
    const int qb   = (TT / 64 - 1) - blockIdx.x;   // reversed: longest first
    const int q0   = qb * 64;
    const int tid  = threadIdx.x;
    const int lane = tid & 31;
    const int warp = tid >> 5;
    const int g    = lane >> 2;
    const int t    = lane & 3;

    __shared__ __align__(16) float sKP[64 * PSTR];  // Ks / Ps overlay
    __shared__ __align__(16) float sV[64 * VSTR];

    float*    Ks   = sKP;
    float*    Ps   = sKP;
    uint32_t* Ks32 = (uint32_t*)sKP;
    uint32_t* Ps32 = (uint32_t*)sKP;
    uint32_t* Vs32 = (uint32_t*)sV;

    const int r0 = warp * 16 + g;
    const int kk = tid >> 1;            // KV row this thread stages
    const int h0 = (tid & 1) * 32;

    // ---- Prefetch K(0) into registers (overlaps Q staging) -----------------
    float4 pf[8];
    {
        const float4* src = (const float4*)(g_K + ((size_t)(b * TT) + kk) * HH + h0);
        #pragma unroll
        for (int j = 0; j < 8; j++) pf[j] = src[j];
    }

    // ---- Stage Q (already QSCALE*log2e-scaled by proj), extract A-frags ----
    {
        int q = tid >> 1;
        const float4* src = (const float4*)(g_Q + (size_t)(b * TT + q0 + q) * HH + h0);
        float* dst = Ps + q * PSTR + h0;
        #pragma unroll
        for (int j = 0; j < 8; j++) {
            float4 v = src[j];
            float4 w;
            w.x = to_tf32(v.x); w.y = to_tf32(v.y);
            w.z = to_tf32(v.z); w.w = to_tf32(v.w);
            *(float4*)(dst + j * 4) = w;
        }
    }
    __syncwarp();   // staging rows are warp-local

    uint32_t qa[8][4];
    #pragma unroll
    for (int ks = 0; ks < 8; ks++) {
        int c = ks * 8 + t;
        qa[ks][0] = Ps32[(r0)     * PSTR + c];
        qa[ks][1] = Ps32[(r0 + 8) * PSTR + c];
        qa[ks][2] = Ps32[(r0)     * PSTR + c + 4];
        qa[ks][3] = Ps32[(r0 + 8) * PSTR + c + 4];
    }

    float o[8][4];
    #pragma unroll
    for (int nt = 0; nt < 8; nt++)
        #pragma unroll
        for (int r = 0; r < 4; r++) o[nt][r] = 0.f;
    float mr0 = -1e30f, mr1 = -1e30f, l0 = 0.f, l1 = 0.f;

    const int ntiles = qb + 1;
    for (int jt = 0; jt < ntiles; jt++) {
        const int k0 = jt * 64;

        __syncthreads();   // prev GEMM2 done with Vs/Ps; Q frags extracted
        // ---- STS K(jt) from prefetch regs (cvt) ----------------------------
        {
            float* dst = Ks + kk * PSTR + h0;
            #pragma unroll
            for (int j = 0; j < 8; j++) {
                float4 v = pf[j];
                float4 w;
                w.x = to_tf32(v.x); w.y = to_tf32(v.y);
                w.z = to_tf32(v.z); w.w = to_tf32(v.w);
                *(float4*)(dst + j * 4) = w;
            }
        }
        // ---- Issue V(jt) LDG now; consumed after GEMM1 ---------------------
        {
            const float4* src = (const float4*)(g_V + ((size_t)(b * TT) + k0 + kk) * HH + h0);
            #pragma unroll
            for (int j = 0; j < 8; j++) pf[j] = src[j];
        }
        __syncthreads();   // Ks visible to all warps

        // ---- GEMM1: S[16x64 per warp] = Qsc @ K^T (V LDG in flight) --------
        float s[8][4];
        #pragma unroll
        for (int nt = 0; nt < 8; nt++)
            #pragma unroll
            for (int r = 0; r < 4; r++) s[nt][r] = 0.f;

        #pragma unroll
        for (int ks = 0; ks < 8; ks++) {
            const int kr = ks * 8;
            #pragma unroll
            for (int nt = 0; nt < 8; nt++) {
                uint32_t bf[2];
                bf[0] = Ks32[(nt * 8 + g) * PSTR + kr + t];
                bf[1] = Ks32[(nt * 8 + g) * PSTR + kr + t + 4];
                mma_tf32(s[nt], qa[ks], bf);
            }
        }

        // ---- Causal mask (diagonal tile only) ------------------------------
        if (jt == qb) {
            #pragma unroll
            for (int nt = 0; nt < 8; nt++) {
                int kc = nt * 8 + 2 * t;
                if (kc     > r0)     s[nt][0] = -1e30f;
                if (kc + 1 > r0)     s[nt][1] = -1e30f;
                if (kc     > r0 + 8) s[nt][2] = -1e30f;
                if (kc + 1 > r0 + 8) s[nt][3] = -1e30f;
            }
        }

        // ---- Online softmax (base-2, registers, quad-shfl reductions) ------
        float mx0 = -1e30f, mx1 = -1e30f;
        #pragma unroll
        for (int nt = 0; nt < 8; nt++) {
            mx0 = fmaxf(mx0, fmaxf(s[nt][0], s[nt][1]));
            mx1 = fmaxf(mx1, fmaxf(s[nt][2], s[nt][3]));
        }
        mx0 = fmaxf(mx0, __shfl_xor_sync(0xffffffffu, mx0, 1));
        mx0 = fmaxf(mx0, __shfl_xor_sync(0xffffffffu, mx0, 2));
        mx1 = fmaxf(mx1, __shfl_xor_sync(0xffffffffu, mx1, 1));
        mx1 = fmaxf(mx1, __shfl_xor_sync(0xffffffffu, mx1, 2));

        float nm0 = fmaxf(mr0, mx0), nm1 = fmaxf(mr1, mx1);
        float a0 = ex2(mr0 - nm0), a1 = ex2(mr1 - nm1);
        mr0 = nm0; mr1 = nm1;

        float ls0 = 0.f, ls1 = 0.f;
        #pragma unroll
        for (int nt = 0; nt < 8; nt++) {
            s[nt][0] = ex2(s[nt][0] - nm0);
            s[nt][1] = ex2(s[nt][1] - nm0);
            s[nt][2] = ex2(s[nt][2] - nm1);
            s[nt][3] = ex2(s[nt][3] - nm1);
            ls0 += s[nt][0] + s[nt][1];
            ls1 += s[nt][2] + s[nt][3];
        }
        ls0 += __shfl_xor_sync(0xffffffffu, ls0, 1);
        ls0 += __shfl_xor_sync(0xffffffffu, ls0, 2);
        ls1 += __shfl_xor_sync(0xffffffffu, ls1, 1);
        ls1 += __shfl_xor_sync(0xffffffffu, ls1, 2);
        l0 = l0 * a0 + ls0;
        l1 = l1 * a1 + ls1;
        #pragma unroll
        for (int nt = 0; nt < 8; nt++) {
            o[nt][0] *= a0; o[nt][1] *= a0;
            o[nt][2] *= a1; o[nt][3] *= a1;
        }

        __syncthreads();   // all warps done reading Ks

        // ---- STS V(jt) from prefetch regs (cvt) ----------------------------
        {
            float* dst = sV + kk * VSTR + h0;
            #pragma unroll
            for (int j = 0; j < 8; j++) {
                float4 v = pf[j];
                float4 w;
                w.x = to_tf32(v.x); w.y = to_tf32(v.y);
                w.z = to_tf32(v.z); w.w = to_tf32(v.w);
                *(float4*)(dst + j * 4) = w;
            }
        }
        // ---- Store P (tf32) into Ps[q][k] ---------------------------------
        #pragma unroll
        for (int nt = 0; nt < 8; nt++) {
            int kc = nt * 8 + 2 * t;
            float2 p0 = make_float2(to_tf32(s[nt][0]), to_tf32(s[nt][1]));
            float2 p1 = make_float2(to_tf32(s[nt][2]), to_tf32(s[nt][3]));
            *(float2*)(Ps + (r0)     * PSTR + kc) = p0;
            *(float2*)(Ps + (r0 + 8) * PSTR + kc) = p1;
        }
        // ---- Issue K(jt+1) LDG; consumed at next tile top (hidden by GEMM2)
        if (jt + 1 < ntiles) {
            const float4* src = (const float4*)(g_K + ((size_t)(b * TT) + k0 + 64 + kk) * HH + h0);
            #pragma unroll
            for (int j = 0; j < 8; j++) pf[j] = src[j];
        }
        __syncthreads();   // Vs + Ps visible to all warps

        // ---- GEMM2: O[16x64 per warp] += P @ V (K LDG in flight) -----------
        #pragma unroll
        for (int ks = 0; ks < 8; ks++) {
            const int kr = ks * 8;
            uint32_t pa[4];
            pa[0] = Ps32[(r0)     * PSTR + kr + t];
            pa[1] = Ps32[(r0 + 8) * PSTR + kr + t];
            pa[2] = Ps32[(r0)     * PSTR + kr + t + 4];
            pa[3] = Ps32[(r0 + 8) * PSTR + kr + t + 4];
            #pragma unroll
            for (int nt = 0; nt < 8; nt++) {
                uint32_t bf[2];
                bf[0] = Vs32[(kr + t)     * VSTR + nt * 8 + g];
                bf[1] = Vs32[(kr + t + 4) * VSTR + nt * 8 + g];
                mma_tf32(o[nt], pa, bf);
            }
        }
    }

    // ---- Normalize + store --------------------------------------------------
    const float inv0 = 1.f / l0;
    const float inv1 = 1.f / l1;
    #pragma unroll
    for (int nt = 0; nt < 8; nt++) {
        int cb = nt * 8 + 2 * t;
        float2 lo = make_float2(o[nt][0] * inv0, o[nt][1] * inv0);
        float2 hi = make_float2(o[nt][2] * inv1, o[nt][3] * inv1);
        *(float2*)(out + (size_t)(b * TT + q0 + r0)     * HH + cb) = lo;
        *(float2*)(out + (size_t)(b * TT + q0 + r0 + 8) * HH + cb) = hi;
    }
}

// ---------------------------------------------------------------------------
extern "C" void kernel_launch(void* const* d_in, const int* in_sizes, int n_in,
                              void* d_out, int out_size) {
    const float* x  = (const float*)d_in[0];
    const float* Wq = (const float*)d_in[1];
    const float* Wk = (const float*)d_in[2];
    const float* Wv = (const float*)d_in[3];
    float* out = (float*)d_out;

    proj_mma<<<dim3(BT / 128, 3), 256>>>(x, Wq, Wk, Wv);
    attn5<<<dim3(TT / 64, BB), 128>>>(out);
}